// round 3
// baseline (speedup 1.0000x reference)
#include <cuda_runtime.h>
#include <math.h>

#define B_ 2
#define T_ 2048
#define DM 2048
#define NH 16
#define HD 128
#define HP_ 8
#define QKV_N 6144
#define M_ (B_*T_)

// ---------------- scratch (device globals: allocation-free) ----------------
__device__ float g_qkv [M_*QKV_N];            // [B*T, 6144]
__device__ float g_gate[M_*DM];               // [B*T, 2048]
__device__ float g_q[2*B_*HP_*T_*HD];         // [branch][b][hp][t][128]
__device__ float g_k[2*B_*HP_*T_*HD];
__device__ float g_v[B_*HP_*T_*2*HD];         // [b][hp][t][256]
__device__ float g_y[2*B_*HP_*T_*2*HD];       // [branch][b][hp][t][256]

// ---------------- fused SGEMM: qkv (N=6144) + gate (N=2048) in one grid ----
// x-tile 0..47 -> C1 = A @ B1 (N1=6144); x-tile 48..63 -> C2 = A @ B2 (N2=2048)
// 128x128 tile, BK=16, 256 threads, 8x8 per-thread microtile, reg prefetch.
__global__ __launch_bounds__(256) void sgemm_fused_kernel(
    const float* __restrict__ A,
    const float* __restrict__ B1, float* __restrict__ C1,
    const float* __restrict__ B2, float* __restrict__ C2,
    int K)
{
    __shared__ float As[16][128];   // transposed A tile: As[k][m]
    __shared__ float Bs[16][128];   // Bs[k][n]
    const int tid = threadIdx.x;
    const int bm = blockIdx.y * 128;

    const float* Bm; float* C; int N, bn;
    if (blockIdx.x < QKV_N / 128) { Bm = B1; C = C1; N = QKV_N; bn = blockIdx.x * 128; }
    else                          { Bm = B2; C = C2; N = DM;    bn = (blockIdx.x - QKV_N / 128) * 128; }

    const int tx = tid & 15, ty = tid >> 4;
    const int tr = ty * 8, tc = tx * 8;
    const int aRow = tid >> 2;          // 0..63
    const int aCol = (tid & 3) << 2;    // 0,4,8,12
    const int bRow = tid >> 5;          // 0..7
    const int bCol = (tid & 31) << 2;   // 0..124

    const float* Ap = A + (long)bm * K;
    const float* Bp = Bm + bn;

    float acc[8][8];
#pragma unroll
    for (int i = 0; i < 8; i++)
#pragma unroll
        for (int j = 0; j < 8; j++) acc[i][j] = 0.f;

    float4 pa0 = *(const float4*)&Ap[(long)aRow * K + aCol];
    float4 pa1 = *(const float4*)&Ap[(long)(aRow + 64) * K + aCol];
    float4 pb0 = *(const float4*)&Bp[(long)bRow * N + bCol];
    float4 pb1 = *(const float4*)&Bp[(long)(bRow + 8) * N + bCol];

    for (int k0 = 0; k0 < K; k0 += 16) {
        As[aCol + 0][aRow]      = pa0.x; As[aCol + 1][aRow]      = pa0.y;
        As[aCol + 2][aRow]      = pa0.z; As[aCol + 3][aRow]      = pa0.w;
        As[aCol + 0][aRow + 64] = pa1.x; As[aCol + 1][aRow + 64] = pa1.y;
        As[aCol + 2][aRow + 64] = pa1.z; As[aCol + 3][aRow + 64] = pa1.w;
        *(float4*)&Bs[bRow][bCol]     = pb0;
        *(float4*)&Bs[bRow + 8][bCol] = pb1;
        __syncthreads();
        const int kn = k0 + 16;
        if (kn < K) {
            pa0 = *(const float4*)&Ap[(long)aRow * K + kn + aCol];
            pa1 = *(const float4*)&Ap[(long)(aRow + 64) * K + kn + aCol];
            pb0 = *(const float4*)&Bp[(long)(kn + bRow) * N + bCol];
            pb1 = *(const float4*)&Bp[(long)(kn + bRow + 8) * N + bCol];
        }
#pragma unroll
        for (int kk = 0; kk < 16; kk++) {
            float4 a0 = *(const float4*)&As[kk][tr];
            float4 a1 = *(const float4*)&As[kk][tr + 4];
            float4 b0 = *(const float4*)&Bs[kk][tc];
            float4 b1 = *(const float4*)&Bs[kk][tc + 4];
            float a[8] = {a0.x, a0.y, a0.z, a0.w, a1.x, a1.y, a1.z, a1.w};
            float b[8] = {b0.x, b0.y, b0.z, b0.w, b1.x, b1.y, b1.z, b1.w};
#pragma unroll
            for (int i = 0; i < 8; i++)
#pragma unroll
                for (int j = 0; j < 8; j++) acc[i][j] = fmaf(a[i], b[j], acc[i][j]);
        }
        __syncthreads();
    }
    float* Cp = C + (long)(bm + tr) * N + bn + tc;
#pragma unroll
    for (int i = 0; i < 8; i++) {
        *(float4*)&Cp[(long)i * N]     = make_float4(acc[i][0], acc[i][1], acc[i][2], acc[i][3]);
        *(float4*)&Cp[(long)i * N + 4] = make_float4(acc[i][4], acc[i][5], acc[i][6], acc[i][7]);
    }
}

// ---------------- prep: rmsnorm(q,k) + RoPE + scatter to attn layout -------
// grid (T, B), 512 threads: warp w handles head w (0..15).
__global__ __launch_bounds__(512) void prep_kernel()
{
    const int t = blockIdx.x, b = blockIdx.y;
    const int w = threadIdx.x >> 5;      // head
    const int lane = threadIdx.x & 31;
    const int branch = w & 1, hp = w >> 1;
    const float* base = g_qkv + ((long)((long)(b * T_ + t) * NH + w)) * (3 * HD);

    // RoPE angles for pair indices j = lane and j = lane+32  (j in 0..63)
    const float coef = 9.2103403719761836f / 64.0f;   // ln(10000)/64
    const float lt = (float)t;
    const float ang0 = lt * __expf(-coef * (float)lane);
    const float ang1 = lt * __expf(-coef * (float)(lane + 32));
    float s0, c0, s1, c1;
    sincosf(ang0, &s0, &c0);
    sincosf(ang1, &s1, &c1);

#pragma unroll
    for (int qk = 0; qk < 2; qk++) {
        const float* src = base + qk * HD;
        float x0 = src[lane], x1 = src[lane + 32], x2 = src[lane + 64], x3 = src[lane + 96];
        float ss = x0 * x0 + x1 * x1 + x2 * x2 + x3 * x3;
#pragma unroll
        for (int off = 16; off; off >>= 1) ss += __shfl_xor_sync(0xffffffffu, ss, off);
        const float r = rsqrtf(ss * (1.0f / 128.0f) + 1e-6f);
        x0 *= r; x1 *= r; x2 *= r; x3 *= r;
        // pairs (lane, lane+64) with j=lane; (lane+32, lane+96) with j=lane+32
        const float o0 =  x0 * c0 + x2 * s0;
        const float o2 = -x0 * s0 + x2 * c0;
        const float o1 =  x1 * c1 + x3 * s1;
        const float o3 = -x1 * s1 + x3 * c1;
        float* dst = (qk == 0 ? g_q : g_k) +
            (((long)(branch * B_ + b) * HP_ + hp) * T_ + t) * HD;
        dst[lane] = o0; dst[lane + 32] = o1; dst[lane + 64] = o2; dst[lane + 96] = o3;
    }
    {   // V: raw copy into [b][hp][t][branch*128 + d]
        const float* vb = base + 2 * HD;
        float* dst = g_v + (((long)b * HP_ + hp) * T_ + t) * (2 * HD) + branch * HD;
        dst[lane]      = vb[lane];
        dst[lane + 32] = vb[lane + 32];
        dst[lane + 64] = vb[lane + 64];
        dst[lane + 96] = vb[lane + 96];
    }
}

// ---------------- flash attention (fp32), causal -----------------------------
// grid (T/64, HP, 2*B) where z = b*2 + branch. 256 threads.
// P buffer stride padded to 68 so PV phase can read P as float4 (4 j at once).
#define PSTRIDE 68
__global__ __launch_bounds__(256) void attn_kernel()
{
    extern __shared__ float sm[];
    float* Qs = sm;                 // [128][64]  (transposed)
    float* Ks = Qs + 128 * 64;      // [128][64]
    float* Vs = Ks + 128 * 64;      // [64][256]
    float* Ps = Vs + 64 * 256;      // [64][PSTRIDE]
    float* Al = Ps + 64 * PSTRIDE;  // [64]
    float* Ll = Al + 64;            // [64]

    const int qb = blockIdx.x;
    const int h  = blockIdx.y;
    const int z  = blockIdx.z;
    const int b = z >> 1, branch = z & 1;
    const float* Qg = g_q + (((long)(branch * B_ + b) * HP_ + h) * T_) * HD;
    const float* Kg = g_k + (((long)(branch * B_ + b) * HP_ + h) * T_) * HD;
    const float* Vg = g_v + (((long)b * HP_ + h) * T_) * (2 * HD);
    float*       Yg = g_y + (((long)(branch * B_ + b) * HP_ + h) * T_) * (2 * HD);

    const int tid = threadIdx.x;
    // load Q block, transposed
    for (int idx = tid; idx < 64 * 32; idx += 256) {
        const int rr = idx >> 5, c4 = (idx & 31) << 2;
        float4 v = *(const float4*)&Qg[(long)(qb * 64 + rr) * HD + c4];
        Qs[(c4 + 0) * 64 + rr] = v.x;
        Qs[(c4 + 1) * 64 + rr] = v.y;
        Qs[(c4 + 2) * 64 + rr] = v.z;
        Qs[(c4 + 3) * 64 + rr] = v.w;
    }
    // S-phase mapping: 16x16 threads, 4x4 tile each
    const int txs = tid & 15, tys = tid >> 4;
    const int i0s = tys * 4, j0s = txs * 4;
    // PV mapping: 8x32 threads, 8 rows x (4 lo + 4 hi) cols each
    const int txp = tid & 31, typ = tid >> 5;
    const int i0p = typ * 8;

    float m_r[4], l_r[4];
#pragma unroll
    for (int r = 0; r < 4; r++) { m_r[r] = -1e30f; l_r[r] = 0.f; }
    float o[8][8];
#pragma unroll
    for (int r = 0; r < 8; r++)
#pragma unroll
        for (int c = 0; c < 8; c++) o[r][c] = 0.f;
    __syncthreads();

    const float scale = 0.08838834764831845f;  // 128^-0.5
    for (int kb = 0; kb <= qb; kb++) {
        // load K (transposed) and V tiles
        for (int idx = tid; idx < 64 * 32; idx += 256) {
            const int rr = idx >> 5, c4 = (idx & 31) << 2;
            float4 v = *(const float4*)&Kg[(long)(kb * 64 + rr) * HD + c4];
            Ks[(c4 + 0) * 64 + rr] = v.x;
            Ks[(c4 + 1) * 64 + rr] = v.y;
            Ks[(c4 + 2) * 64 + rr] = v.z;
            Ks[(c4 + 3) * 64 + rr] = v.w;
        }
        for (int idx = tid; idx < 64 * 64; idx += 256) {
            const int rr = idx >> 6, c4 = (idx & 63) << 2;
            *(float4*)&Vs[rr * 256 + c4] = *(const float4*)&Vg[(long)(kb * 64 + rr) * 256 + c4];
        }
        __syncthreads();

        // S = Q K^T
        float s[4][4];
#pragma unroll
        for (int r = 0; r < 4; r++)
#pragma unroll
            for (int c = 0; c < 4; c++) s[r][c] = 0.f;
#pragma unroll 8
        for (int kk = 0; kk < 128; kk++) {
            float4 aq = *(const float4*)&Qs[kk * 64 + i0s];
            float4 bk = *(const float4*)&Ks[kk * 64 + j0s];
            float av[4] = {aq.x, aq.y, aq.z, aq.w};
            float bv[4] = {bk.x, bk.y, bk.z, bk.w};
#pragma unroll
            for (int r = 0; r < 4; r++)
#pragma unroll
                for (int c = 0; c < 4; c++) s[r][c] = fmaf(av[r], bv[c], s[r][c]);
        }
        // scale + causal mask
        if (kb == qb) {
#pragma unroll
            for (int r = 0; r < 4; r++)
#pragma unroll
                for (int c = 0; c < 4; c++)
                    s[r][c] = (j0s + c > i0s + r) ? -1e30f : s[r][c] * scale;
        } else {
#pragma unroll
            for (int r = 0; r < 4; r++)
#pragma unroll
                for (int c = 0; c < 4; c++) s[r][c] *= scale;
        }
        // online softmax (per-row state redundantly kept across the 16 threads of a row group)
        float rm[4], rs[4], al[4], p[4][4];
#pragma unroll
        for (int r = 0; r < 4; r++) {
            rm[r] = fmaxf(fmaxf(s[r][0], s[r][1]), fmaxf(s[r][2], s[r][3]));
        }
#pragma unroll
        for (int off = 8; off; off >>= 1)
#pragma unroll
            for (int r = 0; r < 4; r++)
                rm[r] = fmaxf(rm[r], __shfl_xor_sync(0xffffffffu, rm[r], off));
#pragma unroll
        for (int r = 0; r < 4; r++) {
            const float mn = fmaxf(m_r[r], rm[r]);
            al[r] = __expf(m_r[r] - mn);
            m_r[r] = mn;
#pragma unroll
            for (int c = 0; c < 4; c++) p[r][c] = __expf(s[r][c] - mn);
            rs[r] = p[r][0] + p[r][1] + p[r][2] + p[r][3];
        }
#pragma unroll
        for (int off = 8; off; off >>= 1)
#pragma unroll
            for (int r = 0; r < 4; r++)
                rs[r] += __shfl_xor_sync(0xffffffffu, rs[r], off);
#pragma unroll
        for (int r = 0; r < 4; r++) l_r[r] = l_r[r] * al[r] + rs[r];

#pragma unroll
        for (int r = 0; r < 4; r++)
            *(float4*)&Ps[(i0s + r) * PSTRIDE + j0s] =
                make_float4(p[r][0], p[r][1], p[r][2], p[r][3]);
        if (txs == 0) {
#pragma unroll
            for (int r = 0; r < 4; r++) Al[i0s + r] = al[r];
        }
        __syncthreads();

        // O = O*alpha + P @ V  (P read as float4: 4 j-columns per load)
#pragma unroll
        for (int r = 0; r < 8; r++) {
            const float a = Al[i0p + r];
#pragma unroll
            for (int c = 0; c < 8; c++) o[r][c] *= a;
        }
        for (int j0 = 0; j0 < 64; j0 += 4) {
            float4 p4[8];
#pragma unroll
            for (int r = 0; r < 8; r++)
                p4[r] = *(const float4*)&Ps[(i0p + r) * PSTRIDE + j0];
#pragma unroll
            for (int jj = 0; jj < 4; jj++) {
                const int j = j0 + jj;
                const float4 vlo = *(const float4*)&Vs[j * 256 + txp * 4];
                const float4 vhi = *(const float4*)&Vs[j * 256 + 128 + txp * 4];
#pragma unroll
                for (int r = 0; r < 8; r++) {
                    const float pv = (jj == 0) ? p4[r].x : (jj == 1) ? p4[r].y
                                   : (jj == 2) ? p4[r].z : p4[r].w;
                    o[r][0] = fmaf(pv, vlo.x, o[r][0]);
                    o[r][1] = fmaf(pv, vlo.y, o[r][1]);
                    o[r][2] = fmaf(pv, vlo.z, o[r][2]);
                    o[r][3] = fmaf(pv, vlo.w, o[r][3]);
                    o[r][4] = fmaf(pv, vhi.x, o[r][4]);
                    o[r][5] = fmaf(pv, vhi.y, o[r][5]);
                    o[r][6] = fmaf(pv, vhi.z, o[r][6]);
                    o[r][7] = fmaf(pv, vhi.w, o[r][7]);
                }
            }
        }
        __syncthreads();
    }

    if (txs == 0) {
#pragma unroll
        for (int r = 0; r < 4; r++) Ll[i0s + r] = l_r[r];
    }
    __syncthreads();
#pragma unroll
    for (int r = 0; r < 8; r++) {
        const float inv = 1.0f / Ll[i0p + r];
        const long row = (long)(qb * 64 + i0p + r);
        *(float4*)&Yg[row * 256 + txp * 4] =
            make_float4(o[r][0] * inv, o[r][1] * inv, o[r][2] * inv, o[r][3] * inv);
        *(float4*)&Yg[row * 256 + 128 + txp * 4] =
            make_float4(o[r][4] * inv, o[r][5] * inv, o[r][6] * inv, o[r][7] * inv);
    }
}

// ---------------- epilogue: diff + silu gate + rmsnorm ----------------------
// grid (T, B), 256 threads: warp w handles head-pair w (0..7).
__global__ __launch_bounds__(256) void final_kernel(
    const float* __restrict__ lq1, const float* __restrict__ lk1,
    const float* __restrict__ lq2, const float* __restrict__ lk2,
    float* __restrict__ out)
{
    const int t = blockIdx.x, b = blockIdx.y;
    const int h = threadIdx.x >> 5, lane = threadIdx.x & 31;
    float d1 = lq1[h * 64 + lane] * lk1[h * 64 + lane]
             + lq1[h * 64 + lane + 32] * lk1[h * 64 + lane + 32];
    float d2 = lq2[h * 64 + lane] * lk2[h * 64 + lane]
             + lq2[h * 64 + lane + 32] * lk2[h * 64 + lane + 32];
#pragma unroll
    for (int off = 16; off; off >>= 1) {
        d1 += __shfl_xor_sync(0xffffffffu, d1, off);
        d2 += __shfl_xor_sync(0xffffffffu, d2, off);
    }
    const float LAMI = 0.8f - 0.6f * expf(-1.8f);
    const float lam = expf(d1) - expf(d2) + LAMI;

    const float* y1 = g_y + (((long)(0 * B_ + b) * HP_ + h) * T_ + t) * 256;
    const float* y2 = g_y + (((long)(1 * B_ + b) * HP_ + h) * T_ + t) * 256;
    const float* gp = g_gate + (long)(b * T_ + t) * DM + h * 256;

    float vals[8]; float ss = 0.f;
#pragma unroll
    for (int i = 0; i < 8; i++) {
        const int d = lane + i * 32;
        const float y = y1[d] - lam * y2[d];
        const float gv = gp[d];
        const float sg = gv / (1.0f + expf(-gv));
        const float v = y * sg;
        vals[i] = v; ss += v * v;
    }
#pragma unroll
    for (int off = 16; off; off >>= 1) ss += __shfl_xor_sync(0xffffffffu, ss, off);
    const float r = rsqrtf(ss * (1.0f / 256.0f) + 1e-6f) * (1.0f - LAMI);

    float* op = out + (long)(b * T_ + t) * DM + h * 256;
#pragma unroll
    for (int i = 0; i < 8; i++) op[lane + i * 32] = vals[i] * r;
}

// ---------------- launch ----------------------------------------------------
extern "C" void kernel_launch(void* const* d_in, const int* in_sizes, int n_in,
                              void* d_out, int out_size)
{
    const float* x    = (const float*)d_in[0];
    const float* Wqkv = (const float*)d_in[1];
    const float* lq1  = (const float*)d_in[2];
    const float* lk1  = (const float*)d_in[3];
    const float* lq2  = (const float*)d_in[4];
    const float* lk2  = (const float*)d_in[5];
    const float* Wg   = (const float*)d_in[6];
    float* out = (float*)d_out;

    float *qkv_p = nullptr, *gate_p = nullptr;
    cudaGetSymbolAddress((void**)&qkv_p, g_qkv);
    cudaGetSymbolAddress((void**)&gate_p, g_gate);

    // fused qkv+gate GEMM: 48 + 16 N-tiles, 32 M-tiles
    dim3 g1(QKV_N / 128 + DM / 128, M_ / 128);
    sgemm_fused_kernel<<<g1, 256>>>(x, Wqkv, qkv_p, Wg, gate_p, DM);

    prep_kernel<<<dim3(T_, B_), 512>>>();

    const size_t shmem = (size_t)(128 * 64 + 128 * 64 + 64 * 256 + 64 * PSTRIDE + 128) * sizeof(float);
    cudaFuncSetAttribute(attn_kernel, cudaFuncAttributeMaxDynamicSharedMemorySize, (int)shmem);
    attn_kernel<<<dim3(T_ / 64, HP_, 2 * B_), 256, shmem>>>();

    final_kernel<<<dim3(T_, B_), 256>>>(lq1, lk1, lq2, lk2, out);
}

// round 6
// speedup vs baseline: 4.4753x; 4.4753x over previous
#include <cuda_runtime.h>
#include <math.h>

#define B_ 2
#define T_ 2048
#define DM 2048
#define NH 16
#define HD 128
#define HP_ 8
#define QKV_N 6144
#define M_ (B_*T_)

// ---------------- scratch (device globals: allocation-free) ----------------
__device__ float g_qkv [M_*QKV_N];            // [B*T, 6144]
__device__ float g_gate[M_*DM];               // [B*T, 2048]
__device__ float g_q[2*B_*HP_*T_*HD];         // [branch][b][hp][t][128]
__device__ float g_k[2*B_*HP_*T_*HD];
__device__ float g_v[B_*HP_*T_*2*HD];         // [b][hp][t][256]
__device__ float g_y[2*B_*HP_*T_*2*HD];       // [branch][b][hp][t][256]

__device__ __forceinline__ float to_tf32(float x) {
    float r;
    asm("cvt.rna.tf32.f32 %0, %1;" : "=f"(r) : "f"(x));
    return r;
}

__device__ __forceinline__ void mma_tf32(float c[4], unsigned a0, unsigned a1,
                                         unsigned a2, unsigned a3,
                                         unsigned b0, unsigned b1)
{
    asm volatile(
        "mma.sync.aligned.m16n8k8.row.col.f32.tf32.tf32.f32 "
        "{%0,%1,%2,%3}, {%4,%5,%6,%7}, {%8,%9}, {%0,%1,%2,%3};"
        : "+f"(c[0]), "+f"(c[1]), "+f"(c[2]), "+f"(c[3])
        : "r"(a0), "r"(a1), "r"(a2), "r"(a3), "r"(b0), "r"(b1));
}

// ---------------- fused TF32 tensor-core GEMM ------------------------------
// x-tile 0..47 -> C1 = A @ B1 (N1=6144); x-tile 48..63 -> C2 = A @ B2 (N2=2048)
// 128x128 tile, BK=32, 256 threads (8 warps), warp = 64x32 via m16n8k8 tf32.
// Global->register prefetch double buffer on the k loop.
__global__ __launch_bounds__(256) void gemm_tf32_fused_kernel(
    const float* __restrict__ A,
    const float* __restrict__ B1, float* __restrict__ C1,
    const float* __restrict__ B2, float* __restrict__ C2,
    int K)
{
    __shared__ float As[128][36];   // [m][k], stride 36 -> frag loads conflict-free
    __shared__ float Bs[32][136];   // [k][n], stride 136 -> frag loads conflict-free

    const int tid = threadIdx.x;
    const int bm = blockIdx.y * 128;

    const float* Bm; float* C; int N, bn;
    if (blockIdx.x < QKV_N / 128) { Bm = B1; C = C1; N = QKV_N; bn = blockIdx.x * 128; }
    else                          { Bm = B2; C = C2; N = DM;    bn = (blockIdx.x - QKV_N / 128) * 128; }

    const int wid = tid >> 5, lane = tid & 31;
    const int wm = wid & 1, wn = wid >> 1;        // warp tile: rows wm*64, cols wn*32
    const int g = lane >> 2, t = lane & 3;        // groupID, threadID_in_group

    const int arow = tid >> 3, acol = (tid & 7) << 2;
    const int brow = tid >> 5, bcol = (tid & 31) << 2;

    float c[4][4][4];
#pragma unroll
    for (int mf = 0; mf < 4; mf++)
#pragma unroll
        for (int nf = 0; nf < 4; nf++)
#pragma unroll
            for (int r = 0; r < 4; r++) c[mf][nf][r] = 0.f;

    float4 pa[4], pb[4];
#pragma unroll
    for (int i = 0; i < 4; i++) {
        pa[i] = *(const float4*)&A [(long)(bm + arow + i * 32) * K + acol];
        pb[i] = *(const float4*)&Bm[(long)(brow + i * 8) * N + bn + bcol];
    }

    for (int k0 = 0; k0 < K; k0 += 32) {
#pragma unroll
        for (int i = 0; i < 4; i++) {
            float4 v = pa[i];
            v.x = to_tf32(v.x); v.y = to_tf32(v.y); v.z = to_tf32(v.z); v.w = to_tf32(v.w);
            *(float4*)&As[arow + i * 32][acol] = v;
            float4 w = pb[i];
            w.x = to_tf32(w.x); w.y = to_tf32(w.y); w.z = to_tf32(w.z); w.w = to_tf32(w.w);
            *(float4*)&Bs[brow + i * 8][bcol] = w;
        }
        __syncthreads();

        const int kn = k0 + 32;
        if (kn < K) {
#pragma unroll
            for (int i = 0; i < 4; i++) {
                pa[i] = *(const float4*)&A [(long)(bm + arow + i * 32) * K + kn + acol];
                pb[i] = *(const float4*)&Bm[(long)(kn + brow + i * 8) * N + bn + bcol];
            }
        }

#pragma unroll
        for (int ks = 0; ks < 4; ks++) {
            const int kb = ks * 8;
            unsigned a[4][4], bfr[4][2];
#pragma unroll
            for (int mf = 0; mf < 4; mf++) {
                const int m0 = wm * 64 + mf * 16;
                a[mf][0] = __float_as_uint(As[m0 + g    ][kb + t    ]);
                a[mf][1] = __float_as_uint(As[m0 + g + 8][kb + t    ]);
                a[mf][2] = __float_as_uint(As[m0 + g    ][kb + t + 4]);
                a[mf][3] = __float_as_uint(As[m0 + g + 8][kb + t + 4]);
            }
#pragma unroll
            for (int nf = 0; nf < 4; nf++) {
                const int n0 = wn * 32 + nf * 8;
                bfr[nf][0] = __float_as_uint(Bs[kb + t    ][n0 + g]);
                bfr[nf][1] = __float_as_uint(Bs[kb + t + 4][n0 + g]);
            }
#pragma unroll
            for (int mf = 0; mf < 4; mf++)
#pragma unroll
                for (int nf = 0; nf < 4; nf++)
                    mma_tf32(c[mf][nf], a[mf][0], a[mf][1], a[mf][2], a[mf][3],
                             bfr[nf][0], bfr[nf][1]);
        }
        __syncthreads();
    }

#pragma unroll
    for (int mf = 0; mf < 4; mf++) {
        const int m0 = bm + wm * 64 + mf * 16;
#pragma unroll
        for (int nf = 0; nf < 4; nf++) {
            const int n0 = bn + wn * 32 + nf * 8 + t * 2;
            *(float2*)&C[(long)(m0 + g    ) * N + n0] = make_float2(c[mf][nf][0], c[mf][nf][1]);
            *(float2*)&C[(long)(m0 + g + 8) * N + n0] = make_float2(c[mf][nf][2], c[mf][nf][3]);
        }
    }
}

// ---------------- prep: rmsnorm(q,k) + RoPE + scatter to attn layout -------
__global__ __launch_bounds__(512) void prep_kernel()
{
    const int t = blockIdx.x, b = blockIdx.y;
    const int w = threadIdx.x >> 5;      // head
    const int lane = threadIdx.x & 31;
    const int branch = w & 1, hp = w >> 1;
    const float* base = g_qkv + ((long)((long)(b * T_ + t) * NH + w)) * (3 * HD);

    const float coef = 9.2103403719761836f / 64.0f;   // ln(10000)/64
    const float lt = (float)t;
    const float ang0 = lt * __expf(-coef * (float)lane);
    const float ang1 = lt * __expf(-coef * (float)(lane + 32));
    float s0, c0, s1, c1;
    sincosf(ang0, &s0, &c0);
    sincosf(ang1, &s1, &c1);

#pragma unroll
    for (int qk = 0; qk < 2; qk++) {
        const float* src = base + qk * HD;
        float x0 = src[lane], x1 = src[lane + 32], x2 = src[lane + 64], x3 = src[lane + 96];
        float ss = x0 * x0 + x1 * x1 + x2 * x2 + x3 * x3;
#pragma unroll
        for (int off = 16; off; off >>= 1) ss += __shfl_xor_sync(0xffffffffu, ss, off);
        const float r = rsqrtf(ss * (1.0f / 128.0f) + 1e-6f);
        x0 *= r; x1 *= r; x2 *= r; x3 *= r;
        const float o0 =  x0 * c0 + x2 * s0;
        const float o2 = -x0 * s0 + x2 * c0;
        const float o1 =  x1 * c1 + x3 * s1;
        const float o3 = -x1 * s1 + x3 * c1;
        float* dst = (qk == 0 ? g_q : g_k) +
            (((long)(branch * B_ + b) * HP_ + hp) * T_ + t) * HD;
        dst[lane] = o0; dst[lane + 32] = o1; dst[lane + 64] = o2; dst[lane + 96] = o3;
    }
    {
        const float* vb = base + 2 * HD;
        float* dst = g_v + (((long)b * HP_ + hp) * T_ + t) * (2 * HD) + branch * HD;
        dst[lane]      = vb[lane];
        dst[lane + 32] = vb[lane + 32];
        dst[lane + 64] = vb[lane + 64];
        dst[lane + 96] = vb[lane + 96];
    }
}

// ---------------- flash attention (tf32 tensor cores), causal ---------------
// grid (T/64, HP, 2*B); 256 threads = 8 warps.
// Warp (rw = wid&3, ch = wid>>2):
//   S phase : rows rw*16..+16, cols ch*32..+32 of the 64x64 S tile
//   PV phase: rows rw*16..+16, d-cols ch*128..+128 of the 64x256 O tile
#define QKSTRIDE 132
#define VSTRIDE  260
#define PSTRIDE  68
__global__ __launch_bounds__(256) void attn_kernel()
{
    extern __shared__ float sm[];
    float* Qs   = sm;                     // [64][QKSTRIDE]
    float* Ks   = Qs + 64 * QKSTRIDE;     // [64][QKSTRIDE]
    float* Vs   = Ks + 64 * QKSTRIDE;     // [64][VSTRIDE]
    float* Ps   = Vs + 64 * VSTRIDE;      // [64][PSTRIDE]
    float* SMax = Ps + 64 * PSTRIDE;      // [64][2]
    float* SSum = SMax + 128;             // [64][2]

    const int qb = blockIdx.x;
    const int h  = blockIdx.y;
    const int z  = blockIdx.z;
    const int b = z >> 1, branch = z & 1;
    const float* Qg = g_q + (((long)(branch * B_ + b) * HP_ + h) * T_) * HD;
    const float* Kg = g_k + (((long)(branch * B_ + b) * HP_ + h) * T_) * HD;
    const float* Vg = g_v + (((long)b * HP_ + h) * T_) * (2 * HD);
    float*       Yg = g_y + (((long)(branch * B_ + b) * HP_ + h) * T_) * (2 * HD);

    const int tid = threadIdx.x;
    const int wid = tid >> 5, lane = tid & 31;
    const int g = lane >> 2, t = lane & 3;
    const int rw = wid & 3, ch = wid >> 2;
    const int i0 = rw * 16;
    const int row0 = i0 + g, row1 = i0 + g + 8;

    // load Q tile (64x128), tf32-rounded
    for (int idx = tid; idx < 64 * 32; idx += 256) {
        const int rr = idx >> 5, c4 = (idx & 31) << 2;
        float4 v = *(const float4*)&Qg[(long)(qb * 64 + rr) * HD + c4];
        v.x = to_tf32(v.x); v.y = to_tf32(v.y); v.z = to_tf32(v.z); v.w = to_tf32(v.w);
        *(float4*)&Qs[rr * QKSTRIDE + c4] = v;
    }

    float m_r[2] = {-1e30f, -1e30f};
    float l_r[2] = {0.f, 0.f};
    float o[16][4];
#pragma unroll
    for (int nf = 0; nf < 16; nf++)
#pragma unroll
        for (int r = 0; r < 4; r++) o[nf][r] = 0.f;
    __syncthreads();

    const float scale = 0.08838834764831845f;  // 128^-0.5
    for (int kb = 0; kb <= qb; kb++) {
        // load K (row-major [j][d]) and V ([j][d]) tiles, tf32-rounded
        for (int idx = tid; idx < 64 * 32; idx += 256) {
            const int rr = idx >> 5, c4 = (idx & 31) << 2;
            float4 v = *(const float4*)&Kg[(long)(kb * 64 + rr) * HD + c4];
            v.x = to_tf32(v.x); v.y = to_tf32(v.y); v.z = to_tf32(v.z); v.w = to_tf32(v.w);
            *(float4*)&Ks[rr * QKSTRIDE + c4] = v;
        }
        for (int idx = tid; idx < 64 * 64; idx += 256) {
            const int rr = idx >> 6, c4 = (idx & 63) << 2;
            float4 v = *(const float4*)&Vg[(long)(kb * 64 + rr) * 256 + c4];
            v.x = to_tf32(v.x); v.y = to_tf32(v.y); v.z = to_tf32(v.z); v.w = to_tf32(v.w);
            *(float4*)&Vs[rr * VSTRIDE + c4] = v;
        }
        __syncthreads();

        // ---- S = Q K^T (warp tile 16x32: 4 n-frags, 16 k-steps) ----
        float s[4][4];
#pragma unroll
        for (int nf = 0; nf < 4; nf++)
#pragma unroll
            for (int r = 0; r < 4; r++) s[nf][r] = 0.f;
#pragma unroll
        for (int ks = 0; ks < 16; ks++) {
            const int kk = ks * 8;
            unsigned a0 = __float_as_uint(Qs[row0 * QKSTRIDE + kk + t]);
            unsigned a1 = __float_as_uint(Qs[row1 * QKSTRIDE + kk + t]);
            unsigned a2 = __float_as_uint(Qs[row0 * QKSTRIDE + kk + t + 4]);
            unsigned a3 = __float_as_uint(Qs[row1 * QKSTRIDE + kk + t + 4]);
#pragma unroll
            for (int nf = 0; nf < 4; nf++) {
                const int n0 = ch * 32 + nf * 8 + g;
                unsigned b0 = __float_as_uint(Ks[n0 * QKSTRIDE + kk + t]);
                unsigned b1 = __float_as_uint(Ks[n0 * QKSTRIDE + kk + t + 4]);
                mma_tf32(s[nf], a0, a1, a2, a3, b0, b1);
            }
        }

        // scale + causal mask. cols of s[nf]: cb+2t (r0,r2), cb+2t+1 (r1,r3)
        const int gi0 = qb * 64 + i0;     // global row base
        const int gj0 = kb * 64 + ch * 32;
#pragma unroll
        for (int nf = 0; nf < 4; nf++) {
            const int jc0 = gj0 + nf * 8 + 2 * t;
            s[nf][0] = (jc0     > gi0 + g    ) ? -1e30f : s[nf][0] * scale;
            s[nf][1] = (jc0 + 1 > gi0 + g    ) ? -1e30f : s[nf][1] * scale;
            s[nf][2] = (jc0     > gi0 + g + 8) ? -1e30f : s[nf][2] * scale;
            s[nf][3] = (jc0 + 1 > gi0 + g + 8) ? -1e30f : s[nf][3] * scale;
        }

        // ---- online softmax ----
        // per-thread partial row max over this warp's 32 cols
        float pm0 = -1e30f, pm1 = -1e30f;
#pragma unroll
        for (int nf = 0; nf < 4; nf++) {
            pm0 = fmaxf(pm0, fmaxf(s[nf][0], s[nf][1]));
            pm1 = fmaxf(pm1, fmaxf(s[nf][2], s[nf][3]));
        }
        pm0 = fmaxf(pm0, __shfl_xor_sync(0xffffffffu, pm0, 1));
        pm0 = fmaxf(pm0, __shfl_xor_sync(0xffffffffu, pm0, 2));
        pm1 = fmaxf(pm1, __shfl_xor_sync(0xffffffffu, pm1, 1));
        pm1 = fmaxf(pm1, __shfl_xor_sync(0xffffffffu, pm1, 2));
        if (t == 0) {
            SMax[row0 * 2 + ch] = pm0;
            SMax[row1 * 2 + ch] = pm1;
        }
        __syncthreads();

        const float fm0 = fmaxf(SMax[row0 * 2], SMax[row0 * 2 + 1]);
        const float fm1 = fmaxf(SMax[row1 * 2], SMax[row1 * 2 + 1]);
        const float mn0 = fmaxf(m_r[0], fm0);
        const float mn1 = fmaxf(m_r[1], fm1);
        const float al0 = __expf(m_r[0] - mn0);
        const float al1 = __expf(m_r[1] - mn1);
        m_r[0] = mn0; m_r[1] = mn1;

        float psum0 = 0.f, psum1 = 0.f;
#pragma unroll
        for (int nf = 0; nf < 4; nf++) {
            float p0 = __expf(s[nf][0] - mn0);
            float p1 = __expf(s[nf][1] - mn0);
            float p2 = __expf(s[nf][2] - mn1);
            float p3 = __expf(s[nf][3] - mn1);
            psum0 += p0 + p1;
            psum1 += p2 + p3;
            const int cb = ch * 32 + nf * 8 + 2 * t;
            *(float2*)&Ps[row0 * PSTRIDE + cb] = make_float2(to_tf32(p0), to_tf32(p1));
            *(float2*)&Ps[row1 * PSTRIDE + cb] = make_float2(to_tf32(p2), to_tf32(p3));
        }
        psum0 += __shfl_xor_sync(0xffffffffu, psum0, 1);
        psum0 += __shfl_xor_sync(0xffffffffu, psum0, 2);
        psum1 += __shfl_xor_sync(0xffffffffu, psum1, 1);
        psum1 += __shfl_xor_sync(0xffffffffu, psum1, 2);
        if (t == 0) {
            SSum[row0 * 2 + ch] = psum0;
            SSum[row1 * 2 + ch] = psum1;
        }
        __syncthreads();

        l_r[0] = l_r[0] * al0 + SSum[row0 * 2] + SSum[row0 * 2 + 1];
        l_r[1] = l_r[1] * al1 + SSum[row1 * 2] + SSum[row1 * 2 + 1];

        // ---- O = O*alpha + P @ V (warp tile 16 x 128: 16 n-frags, 8 k-steps)
#pragma unroll
        for (int nf = 0; nf < 16; nf++) {
            o[nf][0] *= al0; o[nf][1] *= al0;
            o[nf][2] *= al1; o[nf][3] *= al1;
        }
        const int dh = ch * 128;
#pragma unroll
        for (int ks = 0; ks < 8; ks++) {
            const int kk = ks * 8;
            unsigned a0 = __float_as_uint(Ps[row0 * PSTRIDE + kk + t]);
            unsigned a1 = __float_as_uint(Ps[row1 * PSTRIDE + kk + t]);
            unsigned a2 = __float_as_uint(Ps[row0 * PSTRIDE + kk + t + 4]);
            unsigned a3 = __float_as_uint(Ps[row1 * PSTRIDE + kk + t + 4]);
#pragma unroll
            for (int nf = 0; nf < 16; nf++) {
                const int n0 = dh + nf * 8 + g;
                unsigned b0 = __float_as_uint(Vs[(kk + t    ) * VSTRIDE + n0]);
                unsigned b1 = __float_as_uint(Vs[(kk + t + 4) * VSTRIDE + n0]);
                mma_tf32(o[nf], a0, a1, a2, a3, b0, b1);
            }
        }
        __syncthreads();
    }

    // final: divide by l, write out
    const float inv0 = 1.0f / l_r[0];
    const float inv1 = 1.0f / l_r[1];
    const long gr0 = (long)(qb * 64 + row0) * 256;
    const long gr1 = (long)(qb * 64 + row1) * 256;
#pragma unroll
    for (int nf = 0; nf < 16; nf++) {
        const int n0 = ch * 128 + nf * 8 + 2 * t;
        *(float2*)&Yg[gr0 + n0] = make_float2(o[nf][0] * inv0, o[nf][1] * inv0);
        *(float2*)&Yg[gr1 + n0] = make_float2(o[nf][2] * inv1, o[nf][3] * inv1);
    }
}

// ---------------- epilogue: diff + silu gate + rmsnorm ----------------------
__global__ __launch_bounds__(256) void final_kernel(
    const float* __restrict__ lq1, const float* __restrict__ lk1,
    const float* __restrict__ lq2, const float* __restrict__ lk2,
    float* __restrict__ out)
{
    const int t = blockIdx.x, b = blockIdx.y;
    const int h = threadIdx.x >> 5, lane = threadIdx.x & 31;
    float d1 = lq1[h * 64 + lane] * lk1[h * 64 + lane]
             + lq1[h * 64 + lane + 32] * lk1[h * 64 + lane + 32];
    float d2 = lq2[h * 64 + lane] * lk2[h * 64 + lane]
             + lq2[h * 64 + lane + 32] * lk2[h * 64 + lane + 32];
#pragma unroll
    for (int off = 16; off; off >>= 1) {
        d1 += __shfl_xor_sync(0xffffffffu, d1, off);
        d2 += __shfl_xor_sync(0xffffffffu, d2, off);
    }
    const float LAMI = 0.8f - 0.6f * expf(-1.8f);
    const float lam = expf(d1) - expf(d2) + LAMI;

    const float* y1 = g_y + (((long)(0 * B_ + b) * HP_ + h) * T_ + t) * 256;
    const float* y2 = g_y + (((long)(1 * B_ + b) * HP_ + h) * T_ + t) * 256;
    const float* gp = g_gate + (long)(b * T_ + t) * DM + h * 256;

    float vals[8]; float ss = 0.f;
#pragma unroll
    for (int i = 0; i < 8; i++) {
        const int d = lane + i * 32;
        const float y = y1[d] - lam * y2[d];
        const float gv = gp[d];
        const float sg = gv / (1.0f + expf(-gv));
        const float v = y * sg;
        vals[i] = v; ss += v * v;
    }
#pragma unroll
    for (int off = 16; off; off >>= 1) ss += __shfl_xor_sync(0xffffffffu, ss, off);
    const float r = rsqrtf(ss * (1.0f / 256.0f) + 1e-6f) * (1.0f - LAMI);

    float* op = out + (long)(b * T_ + t) * DM + h * 256;
#pragma unroll
    for (int i = 0; i < 8; i++) op[lane + i * 32] = vals[i] * r;
}

// ---------------- launch ----------------------------------------------------
extern "C" void kernel_launch(void* const* d_in, const int* in_sizes, int n_in,
                              void* d_out, int out_size)
{
    const float* x    = (const float*)d_in[0];
    const float* Wqkv = (const float*)d_in[1];
    const float* lq1  = (const float*)d_in[2];
    const float* lk1  = (const float*)d_in[3];
    const float* lq2  = (const float*)d_in[4];
    const float* lk2  = (const float*)d_in[5];
    const float* Wg   = (const float*)d_in[6];
    float* out = (float*)d_out;

    float *qkv_p = nullptr, *gate_p = nullptr;
    cudaGetSymbolAddress((void**)&qkv_p, g_qkv);
    cudaGetSymbolAddress((void**)&gate_p, g_gate);

    // fused qkv+gate GEMM on tensor cores: 48 + 16 N-tiles, 32 M-tiles
    dim3 g1(QKV_N / 128 + DM / 128, M_ / 128);
    gemm_tf32_fused_kernel<<<g1, 256>>>(x, Wqkv, qkv_p, Wg, gate_p, DM);

    prep_kernel<<<dim3(T_, B_), 512>>>();

    const size_t shmem = (size_t)(64 * QKSTRIDE * 2 + 64 * VSTRIDE + 64 * PSTRIDE + 256)
                         * sizeof(float);
    cudaFuncSetAttribute(attn_kernel, cudaFuncAttributeMaxDynamicSharedMemorySize, (int)shmem);
    attn_kernel<<<dim3(T_ / 64, HP_, 2 * B_), 256, shmem>>>();

    final_kernel<<<dim3(T_, B_), 256>>>(lq1, lk1, lq2, lk2, out);
}